// round 5
// baseline (speedup 1.0000x reference)
#include <cuda_runtime.h>

// Problem constants (fixed by the dataset)
#define BATCH   2048
#define LATD    32
#define HID     256
#define DIM     20
#define TSTEPS  512

#define ROWS    16                 // batch rows per CTA
#define RPT     8                  // rows per thread (2 halves)
#define RP      18                 // padded SMEM row stride (even: 8B-aligned ull loads)
#define NCTA    (BATCH / ROWS)     // 128 CTAs
#define NT      512                // 2 halves x 256 units

typedef unsigned long long ull;

// ---------------- packed weight scratch (repacked once per launch) ----------------
// Layout: A[k][unit][gate], gate fastest (float4 per (k,unit)).
__device__ float g_A0x[DIM * 4 * HID];
__device__ float g_A0h[HID * 4 * HID];
__device__ float g_A1x[HID * 4 * HID];
__device__ float g_A1h[HID * 4 * HID];
__device__ float g_PT [HID * DIM];         // w_proj^T: PT[k][d]

// ---------------- packed fp32x2 helpers ----------------
__device__ __forceinline__ ull dup2(float w) {
    ull d; asm("mov.b64 %0, {%1, %1};" : "=l"(d) : "f"(w)); return d;
}
__device__ __forceinline__ ull fma2(ull a, ull b, ull c) {
    ull d; asm("fma.rn.f32x2 %0, %1, %2, %3;" : "=l"(d) : "l"(a), "l"(b), "l"(c)); return d;
}
__device__ __forceinline__ float2 unpack2(ull v) {
    float2 f; asm("mov.b64 {%0, %1}, %2;" : "=f"(f.x), "=f"(f.y) : "l"(v)); return f;
}
__device__ __forceinline__ ull pack2(float a, float b) {
    ull d; asm("mov.b64 %0, {%1, %2};" : "=l"(d) : "f"(a), "f"(b)); return d;
}

// ---------------- saturation-safe fast transcendentals ----------------
__device__ __forceinline__ float sigm(float x) {
    return __fdividef(1.f, 1.f + __expf(-x));
}
__device__ __forceinline__ float tanh_(float x) {
    float e = __expf(2.f * x);
    return 1.f - __fdividef(2.f, e + 1.f);
}

// ---------------- weight repack kernel ----------------
__global__ void repack_kernel(const float* __restrict__ w_ih0,
                              const float* __restrict__ w_hh0,
                              const float* __restrict__ w_ih1,
                              const float* __restrict__ w_hh1,
                              const float* __restrict__ w_proj) {
    const int stride = gridDim.x * blockDim.x;
    const int base   = blockIdx.x * blockDim.x + threadIdx.x;
    for (int idx = base; idx < DIM * HID * 4; idx += stride) {
        int k = idx / (HID * 4), ug = idx % (HID * 4), u = ug >> 2, g = ug & 3;
        g_A0x[idx] = w_ih0[(g * HID + u) * DIM + k];
    }
    for (int idx = base; idx < HID * HID * 4; idx += stride) {
        int k = idx / (HID * 4), ug = idx % (HID * 4), u = ug >> 2, g = ug & 3;
        int src = (g * HID + u) * HID + k;
        g_A0h[idx] = w_hh0[src];
        g_A1x[idx] = w_ih1[src];
        g_A1h[idx] = w_hh1[src];
    }
    for (int idx = base; idx < HID * DIM; idx += stride) {
        int k = idx / DIM, d = idx % DIM;
        g_PT[idx] = w_proj[d * HID + k];
    }
}

// ---------------- gate GEMM: acc[g][rp] += A[k][unit][g] * hs[k][rb+2rp .. rb+2rp+1] ----------------
template <int K>
__device__ __forceinline__ void gemm_packed(const float* __restrict__ wp,
                                            const float* __restrict__ hs,
                                            int unit, int rb, ull (&acc)[4][4]) {
    const float4* wv = reinterpret_cast<const float4*>(wp) + unit;
    #pragma unroll 4
    for (int k = 0; k < K; ++k) {
        float4 w4 = __ldg(wv + (size_t)k * HID);     // coalesced LDG.128 per warp
        const float* hp = hs + k * RP + rb;
        ull h2[4];
        #pragma unroll
        for (int rp = 0; rp < 4; ++rp)
            h2[rp] = *reinterpret_cast<const ull*>(hp + 2 * rp);
        ull w0 = dup2(w4.x), w1 = dup2(w4.y), w2 = dup2(w4.z), w3 = dup2(w4.w);
        #pragma unroll
        for (int rp = 0; rp < 4; ++rp) {
            acc[0][rp] = fma2(h2[rp], w0, acc[0][rp]);
            acc[1][rp] = fma2(h2[rp], w1, acc[1][rp]);
            acc[2][rp] = fma2(h2[rp], w2, acc[2][rp]);
            acc[3][rp] = fma2(h2[rp], w3, acc[3][rp]);
        }
    }
}

__device__ __forceinline__ void cell_update(ull (&acc)[4][4],
                                            float (&c)[RPT], float (&hnew)[RPT]) {
    #pragma unroll
    for (int rp = 0; rp < 4; ++rp) {
        float2 gi = unpack2(acc[0][rp]);
        float2 gf = unpack2(acc[1][rp]);
        float2 gg = unpack2(acc[2][rp]);
        float2 go = unpack2(acc[3][rp]);
        {
            int r = 2 * rp;
            float cc = sigm(gf.x) * c[r] + sigm(gi.x) * tanh_(gg.x);
            c[r] = cc;  hnew[r] = sigm(go.x) * tanh_(cc);
        }
        {
            int r = 2 * rp + 1;
            float cc = sigm(gf.y) * c[r] + sigm(gi.y) * tanh_(gg.y);
            c[r] = cc;  hnew[r] = sigm(go.y) * tanh_(cc);
        }
    }
}

__global__ void __launch_bounds__(NT, 1)
decoder_kernel(const float* __restrict__ z,
               const float* __restrict__ w_lh, const float* __restrict__ b_lh,
               const float* __restrict__ w_lc, const float* __restrict__ b_lc,
               const float* __restrict__ b_ih0, const float* __restrict__ b_hh0,
               const float* __restrict__ b_ih1, const float* __restrict__ b_hh1,
               const float* __restrict__ b_proj,
               float* __restrict__ out) {
    __shared__ __align__(16) float h0_s[HID * RP];
    __shared__ __align__(16) float h1_s[HID * RP];
    __shared__ __align__(16) float x_s[DIM * RP];
    __shared__ __align__(16) float z_s[ROWS * LATD];

    const int tid  = threadIdx.x;
    const int unit = tid & (HID - 1);     // 0..255
    const int half = tid >> 8;            // 0..1
    const int rb   = half * RPT;          // row base within CTA slab
    const int r0   = blockIdx.x * ROWS;

    // ---- load z slab, zero x0 ----
    z_s[tid] = z[(size_t)(r0 + tid / LATD) * LATD + (tid % LATD)];
    for (int i = tid; i < DIM * RP; i += NT) x_s[i] = 0.f;
    __syncthreads();

    // ---- init h/c : h_init = z @ w_lh^T + b_lh ; reshape(B,2,H) ----
    float c0r[RPT], c1r[RPT];
    {
        float h0v[RPT], h1v[RPT];
        #pragma unroll
        for (int r = 0; r < RPT; ++r) {
            h0v[r] = b_lh[unit];  h1v[r] = b_lh[HID + unit];
            c0r[r] = b_lc[unit];  c1r[r] = b_lc[HID + unit];
        }
        const float* wl0 = w_lh + (size_t)unit * LATD;
        const float* wl1 = w_lh + (size_t)(HID + unit) * LATD;
        const float* wc0 = w_lc + (size_t)unit * LATD;
        const float* wc1 = w_lc + (size_t)(HID + unit) * LATD;
        for (int k = 0; k < LATD; ++k) {
            float a0 = wl0[k], a1 = wl1[k], a2 = wc0[k], a3 = wc1[k];
            #pragma unroll
            for (int r = 0; r < RPT; ++r) {
                float zv = z_s[(rb + r) * LATD + k];
                h0v[r] = fmaf(zv, a0, h0v[r]);
                h1v[r] = fmaf(zv, a1, h1v[r]);
                c0r[r] = fmaf(zv, a2, c0r[r]);
                c1r[r] = fmaf(zv, a3, c1r[r]);
            }
        }
        #pragma unroll
        for (int r = 0; r < RPT; ++r) {
            h0_s[unit * RP + rb + r] = h0v[r];
            h1_s[unit * RP + rb + r] = h1v[r];
        }
    }

    // ---- fused gate biases ----
    float bias0[4], bias1[4];
    #pragma unroll
    for (int g = 0; g < 4; ++g) {
        bias0[g] = b_ih0[g * HID + unit] + b_hh0[g * HID + unit];
        bias1[g] = b_ih1[g * HID + unit] + b_hh1[g * HID + unit];
    }

    // ---- projection mapping: 320 threads, one (row, dim) each ----
    const int pr = tid / DIM;             // 0..15 for tid<320
    const int pd = tid - pr * DIM;        // 0..19
    const bool do_proj = (tid < ROWS * DIM);
    const float pbias = do_proj ? b_proj[pd] : 0.f;

    __syncthreads();

    // =============================== time loop ===============================
    for (int t = 0; t < TSTEPS; ++t) {
        ull acc[4][4];
        float hnew[RPT];

        // ---- layer 0 ----
        #pragma unroll
        for (int g = 0; g < 4; ++g) {
            ull bd = dup2(bias0[g]);
            #pragma unroll
            for (int rp = 0; rp < 4; ++rp) acc[g][rp] = bd;
        }
        gemm_packed<DIM>(g_A0x, x_s, unit, rb, acc);
        gemm_packed<HID>(g_A0h, h0_s, unit, rb, acc);
        cell_update(acc, c0r, hnew);
        __syncthreads();                       // readers of old h0 done
        #pragma unroll
        for (int rp = 0; rp < 4; ++rp)
            *reinterpret_cast<ull*>(h0_s + unit * RP + rb + 2 * rp) =
                pack2(hnew[2 * rp], hnew[2 * rp + 1]);
        __syncthreads();                       // new h0 visible

        // ---- layer 1 ----
        #pragma unroll
        for (int g = 0; g < 4; ++g) {
            ull bd = dup2(bias1[g]);
            #pragma unroll
            for (int rp = 0; rp < 4; ++rp) acc[g][rp] = bd;
        }
        gemm_packed<HID>(g_A1x, h0_s, unit, rb, acc);
        gemm_packed<HID>(g_A1h, h1_s, unit, rb, acc);
        cell_update(acc, c1r, hnew);
        __syncthreads();                       // readers of old h1 done
        #pragma unroll
        for (int rp = 0; rp < 4; ++rp)
            *reinterpret_cast<ull*>(h1_s + unit * RP + rb + 2 * rp) =
                pack2(hnew[2 * rp], hnew[2 * rp + 1]);
        __syncthreads();                       // new h1 visible

        // ---- projection: y = h1 @ w_proj^T + b_proj ; feed back ----
        if (do_proj) {
            float pa = pbias;
            #pragma unroll 8
            for (int k = 0; k < HID; ++k) {
                float wv = __ldg(g_PT + k * DIM + pd);
                pa = fmaf(h1_s[k * RP + pr], wv, pa);
            }
            out[(size_t)(r0 + pr) * TSTEPS * DIM + (size_t)t * DIM + pd] = pa;
            x_s[pd * RP + pr] = pa;
        }
        __syncthreads();                       // next x visible for t+1
    }
}

extern "C" void kernel_launch(void* const* d_in, const int* in_sizes, int n_in,
                              void* d_out, int out_size) {
    const int wbase = (n_in >= 17) ? 3 : 2;

    const float* z      = (const float*)d_in[0];
    const float* w_lh   = (const float*)d_in[wbase + 0];
    const float* b_lh   = (const float*)d_in[wbase + 1];
    const float* w_lc   = (const float*)d_in[wbase + 2];
    const float* b_lc   = (const float*)d_in[wbase + 3];
    const float* w_ih0  = (const float*)d_in[wbase + 4];
    const float* w_hh0  = (const float*)d_in[wbase + 5];
    const float* b_ih0  = (const float*)d_in[wbase + 6];
    const float* b_hh0  = (const float*)d_in[wbase + 7];
    const float* w_ih1  = (const float*)d_in[wbase + 8];
    const float* w_hh1  = (const float*)d_in[wbase + 9];
    const float* b_ih1  = (const float*)d_in[wbase + 10];
    const float* b_hh1  = (const float*)d_in[wbase + 11];
    const float* w_proj = (const float*)d_in[wbase + 12];
    const float* b_proj = (const float*)d_in[wbase + 13];

    repack_kernel<<<256, 256>>>(w_ih0, w_hh0, w_ih1, w_hh1, w_proj);
    decoder_kernel<<<NCTA, NT>>>(z, w_lh, b_lh, w_lc, b_lc,
                                 b_ih0, b_hh0, b_ih1, b_hh1,
                                 b_proj, (float*)d_out);
}

// round 6
// speedup vs baseline: 1.0083x; 1.0083x over previous
#include <cuda_runtime.h>

// Problem constants (fixed by the dataset)
#define BATCH   2048
#define LATD    32
#define HID     256
#define DIM     20
#define TSTEPS  512

#define ROWS    16                 // batch rows per CTA
#define RPT     8                  // rows per thread (2 halves)
#define RP      18                 // padded SMEM row stride (even: 8B-aligned ull loads)
#define NCTA    (BATCH / ROWS)     // 128 CTAs
#define NT      512                // 2 halves x 256 units

typedef unsigned long long ull;

// ---------------- packed weight scratch (repacked once per launch) ----------------
// Layout: A[k][unit][gate], gate fastest (float4 per (k,unit)).
__device__ float g_A0x[DIM * 4 * HID];
__device__ float g_A0h[HID * 4 * HID];
__device__ float g_A1x[HID * 4 * HID];
__device__ float g_A1h[HID * 4 * HID];
__device__ float g_PT [HID * DIM];         // w_proj^T: PT[k][d]

// ---------------- packed fp32x2 helpers ----------------
__device__ __forceinline__ ull dup2(float w) {
    ull d; asm("mov.b64 %0, {%1, %1};" : "=l"(d) : "f"(w)); return d;
}
__device__ __forceinline__ ull fma2(ull a, ull b, ull c) {
    ull d; asm("fma.rn.f32x2 %0, %1, %2, %3;" : "=l"(d) : "l"(a), "l"(b), "l"(c)); return d;
}
__device__ __forceinline__ float2 unpack2(ull v) {
    float2 f; asm("mov.b64 {%0, %1}, %2;" : "=f"(f.x), "=f"(f.y) : "l"(v)); return f;
}
__device__ __forceinline__ ull pack2(float a, float b) {
    ull d; asm("mov.b64 %0, {%1, %2};" : "=l"(d) : "f"(a), "f"(b)); return d;
}

// ---------------- saturation-safe fast transcendentals ----------------
__device__ __forceinline__ float sigm(float x) {
    return __fdividef(1.f, 1.f + __expf(-x));
}
__device__ __forceinline__ float tanh_(float x) {
    float e = __expf(2.f * x);
    return 1.f - __fdividef(2.f, e + 1.f);
}

// ---------------- weight repack kernel ----------------
__global__ void repack_kernel(const float* __restrict__ w_ih0,
                              const float* __restrict__ w_hh0,
                              const float* __restrict__ w_ih1,
                              const float* __restrict__ w_hh1,
                              const float* __restrict__ w_proj) {
    const int stride = gridDim.x * blockDim.x;
    const int base   = blockIdx.x * blockDim.x + threadIdx.x;
    for (int idx = base; idx < DIM * HID * 4; idx += stride) {
        int k = idx / (HID * 4), ug = idx % (HID * 4), u = ug >> 2, g = ug & 3;
        g_A0x[idx] = w_ih0[(g * HID + u) * DIM + k];
    }
    for (int idx = base; idx < HID * HID * 4; idx += stride) {
        int k = idx / (HID * 4), ug = idx % (HID * 4), u = ug >> 2, g = ug & 3;
        int src = (g * HID + u) * HID + k;
        g_A0h[idx] = w_hh0[src];
        g_A1x[idx] = w_ih1[src];
        g_A1h[idx] = w_hh1[src];
    }
    for (int idx = base; idx < HID * DIM; idx += stride) {
        int k = idx / DIM, d = idx % DIM;
        g_PT[idx] = w_proj[d * HID + k];
    }
}

// ---------------- gate GEMM: acc[g][rp] += A[k][unit][g] * hs[k][rb+2rp .. rb+2rp+1] ----------------
template <int K>
__device__ __forceinline__ void gemm_packed(const float* __restrict__ wp,
                                            const float* __restrict__ hs,
                                            int unit, int rb, ull (&acc)[4][4]) {
    const float4* wv = reinterpret_cast<const float4*>(wp) + unit;
    #pragma unroll 4
    for (int k = 0; k < K; ++k) {
        float4 w4 = __ldg(wv + (size_t)k * HID);     // coalesced LDG.128 per warp
        const float* hp = hs + k * RP + rb;
        ull h2[4];
        #pragma unroll
        for (int rp = 0; rp < 4; ++rp)
            h2[rp] = *reinterpret_cast<const ull*>(hp + 2 * rp);
        ull w0 = dup2(w4.x), w1 = dup2(w4.y), w2 = dup2(w4.z), w3 = dup2(w4.w);
        #pragma unroll
        for (int rp = 0; rp < 4; ++rp) {
            acc[0][rp] = fma2(h2[rp], w0, acc[0][rp]);
            acc[1][rp] = fma2(h2[rp], w1, acc[1][rp]);
            acc[2][rp] = fma2(h2[rp], w2, acc[2][rp]);
            acc[3][rp] = fma2(h2[rp], w3, acc[3][rp]);
        }
    }
}

__device__ __forceinline__ void cell_update(ull (&acc)[4][4],
                                            float (&c)[RPT], float (&hnew)[RPT]) {
    #pragma unroll
    for (int rp = 0; rp < 4; ++rp) {
        float2 gi = unpack2(acc[0][rp]);
        float2 gf = unpack2(acc[1][rp]);
        float2 gg = unpack2(acc[2][rp]);
        float2 go = unpack2(acc[3][rp]);
        {
            int r = 2 * rp;
            float cc = sigm(gf.x) * c[r] + sigm(gi.x) * tanh_(gg.x);
            c[r] = cc;  hnew[r] = sigm(go.x) * tanh_(cc);
        }
        {
            int r = 2 * rp + 1;
            float cc = sigm(gf.y) * c[r] + sigm(gi.y) * tanh_(gg.y);
            c[r] = cc;  hnew[r] = sigm(go.y) * tanh_(cc);
        }
    }
}

__global__ void __launch_bounds__(NT, 1)
decoder_kernel(const float* __restrict__ z,
               const float* __restrict__ w_lh, const float* __restrict__ b_lh,
               const float* __restrict__ w_lc, const float* __restrict__ b_lc,
               const float* __restrict__ b_ih0, const float* __restrict__ b_hh0,
               const float* __restrict__ b_ih1, const float* __restrict__ b_hh1,
               const float* __restrict__ b_proj,
               float* __restrict__ out) {
    __shared__ __align__(16) float h0_s[HID * RP];
    __shared__ __align__(16) float h1_s[HID * RP];
    __shared__ __align__(16) float x_s[DIM * RP];
    __shared__ __align__(16) float z_s[ROWS * LATD];

    const int tid  = threadIdx.x;
    const int unit = tid & (HID - 1);     // 0..255
    const int half = tid >> 8;            // 0..1
    const int rb   = half * RPT;          // row base within CTA slab
    const int r0   = blockIdx.x * ROWS;

    // ---- load z slab, zero x0 ----
    z_s[tid] = z[(size_t)(r0 + tid / LATD) * LATD + (tid % LATD)];
    for (int i = tid; i < DIM * RP; i += NT) x_s[i] = 0.f;
    __syncthreads();

    // ---- init h/c : h_init = z @ w_lh^T + b_lh ; reshape(B,2,H) ----
    float c0r[RPT], c1r[RPT];
    {
        float h0v[RPT], h1v[RPT];
        #pragma unroll
        for (int r = 0; r < RPT; ++r) {
            h0v[r] = b_lh[unit];  h1v[r] = b_lh[HID + unit];
            c0r[r] = b_lc[unit];  c1r[r] = b_lc[HID + unit];
        }
        const float* wl0 = w_lh + (size_t)unit * LATD;
        const float* wl1 = w_lh + (size_t)(HID + unit) * LATD;
        const float* wc0 = w_lc + (size_t)unit * LATD;
        const float* wc1 = w_lc + (size_t)(HID + unit) * LATD;
        for (int k = 0; k < LATD; ++k) {
            float a0 = wl0[k], a1 = wl1[k], a2 = wc0[k], a3 = wc1[k];
            #pragma unroll
            for (int r = 0; r < RPT; ++r) {
                float zv = z_s[(rb + r) * LATD + k];
                h0v[r] = fmaf(zv, a0, h0v[r]);
                h1v[r] = fmaf(zv, a1, h1v[r]);
                c0r[r] = fmaf(zv, a2, c0r[r]);
                c1r[r] = fmaf(zv, a3, c1r[r]);
            }
        }
        #pragma unroll
        for (int r = 0; r < RPT; ++r) {
            h0_s[unit * RP + rb + r] = h0v[r];
            h1_s[unit * RP + rb + r] = h1v[r];
        }
    }

    // ---- fused gate biases ----
    float bias0[4], bias1[4];
    #pragma unroll
    for (int g = 0; g < 4; ++g) {
        bias0[g] = b_ih0[g * HID + unit] + b_hh0[g * HID + unit];
        bias1[g] = b_ih1[g * HID + unit] + b_hh1[g * HID + unit];
    }

    // ---- projection mapping: 320 threads, one (row, dim) each ----
    const int pr = tid / DIM;             // 0..15 for tid<320
    const int pd = tid - pr * DIM;        // 0..19
    const bool do_proj = (tid < ROWS * DIM);
    const float pbias = do_proj ? b_proj[pd] : 0.f;

    __syncthreads();

    // =============================== time loop ===============================
    for (int t = 0; t < TSTEPS; ++t) {
        ull acc[4][4];
        float hnew[RPT];

        // ---- layer 0 ----
        #pragma unroll
        for (int g = 0; g < 4; ++g) {
            ull bd = dup2(bias0[g]);
            #pragma unroll
            for (int rp = 0; rp < 4; ++rp) acc[g][rp] = bd;
        }
        gemm_packed<DIM>(g_A0x, x_s, unit, rb, acc);
        gemm_packed<HID>(g_A0h, h0_s, unit, rb, acc);
        cell_update(acc, c0r, hnew);
        __syncthreads();                       // readers of old h0 done
        #pragma unroll
        for (int rp = 0; rp < 4; ++rp)
            *reinterpret_cast<ull*>(h0_s + unit * RP + rb + 2 * rp) =
                pack2(hnew[2 * rp], hnew[2 * rp + 1]);
        __syncthreads();                       // new h0 visible

        // ---- layer 1 ----
        #pragma unroll
        for (int g = 0; g < 4; ++g) {
            ull bd = dup2(bias1[g]);
            #pragma unroll
            for (int rp = 0; rp < 4; ++rp) acc[g][rp] = bd;
        }
        gemm_packed<HID>(g_A1x, h0_s, unit, rb, acc);
        gemm_packed<HID>(g_A1h, h1_s, unit, rb, acc);
        cell_update(acc, c1r, hnew);
        __syncthreads();                       // readers of old h1 done
        #pragma unroll
        for (int rp = 0; rp < 4; ++rp)
            *reinterpret_cast<ull*>(h1_s + unit * RP + rb + 2 * rp) =
                pack2(hnew[2 * rp], hnew[2 * rp + 1]);
        __syncthreads();                       // new h1 visible

        // ---- projection: y = h1 @ w_proj^T + b_proj ; feed back ----
        if (do_proj) {
            float pa = pbias;
            #pragma unroll 8
            for (int k = 0; k < HID; ++k) {
                float wv = __ldg(g_PT + k * DIM + pd);
                pa = fmaf(h1_s[k * RP + pr], wv, pa);
            }
            out[(size_t)(r0 + pr) * TSTEPS * DIM + (size_t)t * DIM + pd] = pa;
            x_s[pd * RP + pr] = pa;
        }
        __syncthreads();                       // next x visible for t+1
    }
}

extern "C" void kernel_launch(void* const* d_in, const int* in_sizes, int n_in,
                              void* d_out, int out_size) {
    const int wbase = (n_in >= 17) ? 3 : 2;

    const float* z      = (const float*)d_in[0];
    const float* w_lh   = (const float*)d_in[wbase + 0];
    const float* b_lh   = (const float*)d_in[wbase + 1];
    const float* w_lc   = (const float*)d_in[wbase + 2];
    const float* b_lc   = (const float*)d_in[wbase + 3];
    const float* w_ih0  = (const float*)d_in[wbase + 4];
    const float* w_hh0  = (const float*)d_in[wbase + 5];
    const float* b_ih0  = (const float*)d_in[wbase + 6];
    const float* b_hh0  = (const float*)d_in[wbase + 7];
    const float* w_ih1  = (const float*)d_in[wbase + 8];
    const float* w_hh1  = (const float*)d_in[wbase + 9];
    const float* b_ih1  = (const float*)d_in[wbase + 10];
    const float* b_hh1  = (const float*)d_in[wbase + 11];
    const float* w_proj = (const float*)d_in[wbase + 12];
    const float* b_proj = (const float*)d_in[wbase + 13];

    repack_kernel<<<256, 256>>>(w_ih0, w_hh0, w_ih1, w_hh1, w_proj);
    decoder_kernel<<<NCTA, NT>>>(z, w_lh, b_lh, w_lc, b_lc,
                                 b_ih0, b_hh0, b_ih1, b_hh1,
                                 b_proj, (float*)d_out);
}

// round 7
// speedup vs baseline: 1.5997x; 1.5865x over previous
#include <cuda_runtime.h>
#include <cuda_bf16.h>
#include <cstdint>

#define BATCH   2048
#define LATD    32
#define HID     256
#define DIM     20
#define TST     512

#define ROWS    32
#define NCTA    (BATCH / ROWS)     // 64
#define NT      512
#define NWARP   16

#define KS0     18                 // layer0: cols 0..287  (x|1|0|h0)
#define KS1     33                 // layer1: cols 16..543 (..|1|..|h0|h1)
#define AS      552                // u16 elements per activation row
#define ROWB    (AS * 2)           // 1104 bytes per row
#define MTOFF   (16 * ROWB)        // m-tile 1 byte offset
#define H0C     32
#define H1C     288

#define SMEM_BYTES (32*AS*2*2 + 8*32*33*4 + ROWS*LATD*4)   // 108544

// ---------------- fragment-major packed weights (repacked each launch) ----------------
__device__ uint4 g_W0[NWARP * KS0 * 8 * 32];
__device__ uint4 g_W1[NWARP * KS1 * 8 * 32];
__device__ uint4 g_PJ[8 * 2 * 4 * 32];

// ---------------- helpers ----------------
__device__ __forceinline__ float sigm(float x) {
    return __fdividef(1.f, 1.f + __expf(-x));
}
__device__ __forceinline__ float tanh_(float x) {
    float e = __expf(2.f * x);
    return 1.f - __fdividef(2.f, e + 1.f);
}
__device__ __forceinline__ void split2(float x, unsigned short& hi, unsigned short& lo) {
    __nv_bfloat16 h = __float2bfloat16_rn(x);
    hi = __bfloat16_as_ushort(h);
    lo = __bfloat16_as_ushort(__float2bfloat16_rn(x - __bfloat162float(h)));
}
__device__ __forceinline__ uint32_t smem_u32(const void* p) {
    uint32_t a;
    asm("{ .reg .u64 t; cvta.to.shared.u64 t, %1; cvt.u32.u64 %0, t; }" : "=r"(a) : "l"(p));
    return a;
}
__device__ __forceinline__ void ldsm4(uint32_t& r0, uint32_t& r1, uint32_t& r2, uint32_t& r3,
                                      uint32_t a) {
    asm volatile("ldmatrix.sync.aligned.m8n8.x4.shared.b16 {%0,%1,%2,%3}, [%4];"
                 : "=r"(r0), "=r"(r1), "=r"(r2), "=r"(r3) : "r"(a));
}
__device__ __forceinline__ void mma16816(float* c, uint32_t a0, uint32_t a1, uint32_t a2,
                                         uint32_t a3, uint32_t b0, uint32_t b1) {
    asm volatile(
        "mma.sync.aligned.m16n8k16.row.col.f32.bf16.bf16.f32 "
        "{%0,%1,%2,%3}, {%4,%5,%6,%7}, {%8,%9}, {%0,%1,%2,%3};"
        : "+f"(c[0]), "+f"(c[1]), "+f"(c[2]), "+f"(c[3])
        : "r"(a0), "r"(a1), "r"(a2), "r"(a3), "r"(b0), "r"(b1));
}

// ---------------- repack: weight element accessors (kc = activation column) ----------------
__device__ __forceinline__ float W0val(int kc, int n,
                                       const float* w_ih0, const float* w_hh0,
                                       const float* b_ih0, const float* b_hh0) {
    int u = n >> 2, g = n & 3, row = g * HID + u;
    if (kc < DIM)  return w_ih0[row * DIM + kc];
    if (kc == 20)  return b_ih0[row] + b_hh0[row];
    if (kc < 32)   return 0.f;
    return w_hh0[row * HID + (kc - 32)];
}
__device__ __forceinline__ float W1val(int kc, int n,
                                       const float* w_ih1, const float* w_hh1,
                                       const float* b_ih1, const float* b_hh1) {
    int u = n >> 2, g = n & 3, row = g * HID + u;
    if (kc == 20)  return b_ih1[row] + b_hh1[row];
    if (kc >= 288) return w_hh1[row * HID + (kc - 288)];
    if (kc >= 32)  return w_ih1[row * HID + (kc - 32)];
    return 0.f;
}
__device__ __forceinline__ uint4 pack_frag(float e00, float e01, float e10, float e11) {
    unsigned short h00, l00, h01, l01, h10, l10, h11, l11;
    split2(e00, h00, l00); split2(e01, h01, l01);
    split2(e10, h10, l10); split2(e11, h11, l11);
    uint4 v;
    v.x = (uint32_t)h00 | ((uint32_t)h01 << 16);
    v.y = (uint32_t)h10 | ((uint32_t)h11 << 16);
    v.z = (uint32_t)l00 | ((uint32_t)l01 << 16);
    v.w = (uint32_t)l10 | ((uint32_t)l11 << 16);
    return v;
}

__global__ void repack_kernel(const float* __restrict__ w_ih0, const float* __restrict__ w_hh0,
                              const float* __restrict__ b_ih0, const float* __restrict__ b_hh0,
                              const float* __restrict__ w_ih1, const float* __restrict__ w_hh1,
                              const float* __restrict__ b_ih1, const float* __restrict__ b_hh1,
                              const float* __restrict__ w_proj) {
    const int stride = gridDim.x * blockDim.x;
    const int base   = blockIdx.x * blockDim.x + threadIdx.x;

    const int N0 = NWARP * KS0 * 8 * 32;
    for (int idx = base; idx < N0; idx += stride) {
        int lane = idx & 31, t = idx >> 5;
        int nt = t & 7; t >>= 3;
        int ks = t % KS0, w = t / KS0;
        int n  = w * 64 + nt * 8 + (lane >> 2);
        int kc = ks * 16 + (lane & 3) * 2;
        g_W0[idx] = pack_frag(W0val(kc,     n, w_ih0, w_hh0, b_ih0, b_hh0),
                              W0val(kc + 1, n, w_ih0, w_hh0, b_ih0, b_hh0),
                              W0val(kc + 8, n, w_ih0, w_hh0, b_ih0, b_hh0),
                              W0val(kc + 9, n, w_ih0, w_hh0, b_ih0, b_hh0));
    }
    const int N1 = NWARP * KS1 * 8 * 32;
    for (int idx = base; idx < N1; idx += stride) {
        int lane = idx & 31, t = idx >> 5;
        int nt = t & 7; t >>= 3;
        int ks = t % KS1, w = t / KS1;
        int n  = w * 64 + nt * 8 + (lane >> 2);
        int kc = 16 + ks * 16 + (lane & 3) * 2;
        g_W1[idx] = pack_frag(W1val(kc,     n, w_ih1, w_hh1, b_ih1, b_hh1),
                              W1val(kc + 1, n, w_ih1, w_hh1, b_ih1, b_hh1),
                              W1val(kc + 8, n, w_ih1, w_hh1, b_ih1, b_hh1),
                              W1val(kc + 9, n, w_ih1, w_hh1, b_ih1, b_hh1));
    }
    const int NP = 8 * 2 * 4 * 32;
    for (int idx = base; idx < NP; idx += stride) {
        int lane = idx & 31, t = idx >> 5;
        int nt = t & 3; t >>= 2;
        int ks = t & 1, w = t >> 1;
        int n  = nt * 8 + (lane >> 2);
        int kc = w * 32 + ks * 16 + (lane & 3) * 2;
        float e00 = (n < DIM) ? w_proj[n * HID + kc]     : 0.f;
        float e01 = (n < DIM) ? w_proj[n * HID + kc + 1] : 0.f;
        float e10 = (n < DIM) ? w_proj[n * HID + kc + 8] : 0.f;
        float e11 = (n < DIM) ? w_proj[n * HID + kc + 9] : 0.f;
        g_PJ[idx] = pack_frag(e00, e01, e10, e11);
    }
}

// ---------------- 3-pass bf16-split MMA over one half (4 n-tiles, 2 m-tiles) ----------------
template <int KSTEPS, int KSTRIDE>
__device__ __forceinline__ void mma_half(uint32_t aHi, uint32_t aLo,
                                         const uint4* __restrict__ wf,
                                         float (&acc)[2][4][4]) {
    #pragma unroll
    for (int mt = 0; mt < 2; ++mt)
        #pragma unroll
        for (int n = 0; n < 4; ++n)
            #pragma unroll
            for (int i = 0; i < 4; ++i) acc[mt][n][i] = 0.f;

    #pragma unroll 2
    for (int ks = 0; ks < KSTEPS; ++ks) {
        uint32_t h0, h1, h2, h3, h4, h5, h6, h7;
        uint32_t l0, l1, l2, l3, l4, l5, l6, l7;
        ldsm4(h0, h1, h2, h3, aHi + ks * 32);
        ldsm4(h4, h5, h6, h7, aHi + MTOFF + ks * 32);
        ldsm4(l0, l1, l2, l3, aLo + ks * 32);
        ldsm4(l4, l5, l6, l7, aLo + MTOFF + ks * 32);
        #pragma unroll
        for (int n = 0; n < 4; ++n) {
            uint4 B = __ldg(wf + (size_t)ks * KSTRIDE + n * 32);
            mma16816(acc[0][n], h0, h1, h2, h3, B.x, B.y);   // hiA*hiB
            mma16816(acc[0][n], l0, l1, l2, l3, B.x, B.y);   // loA*hiB
            mma16816(acc[0][n], h0, h1, h2, h3, B.z, B.w);   // hiA*loB
            mma16816(acc[1][n], h4, h5, h6, h7, B.x, B.y);
            mma16816(acc[1][n], l4, l5, l6, l7, B.x, B.y);
            mma16816(acc[1][n], h4, h5, h6, h7, B.z, B.w);
        }
    }
}

// ---------------- LSTM epilogue: gate regroup via lane-pair shuffle ----------------
__device__ __forceinline__ void lstm_epi(float (&acc)[2][4][4], int half, int odd,
                                         float (&cs)[2][8], uint32_t (&hp)[2][8]) {
    #pragma unroll
    for (int mt = 0; mt < 2; ++mt) {
        #pragma unroll
        for (int n = 0; n < 4; ++n) {
            float a0 = acc[mt][n][0], a1 = acc[mt][n][1];
            float a2 = acc[mt][n][2], a3 = acc[mt][n][3];
            float t0 = __shfl_xor_sync(0xffffffffu, a0, 1);
            float t1 = __shfl_xor_sync(0xffffffffu, a1, 1);
            float t2 = __shfl_xor_sync(0xffffffffu, a2, 1);
            float t3 = __shfl_xor_sync(0xffffffffu, a3, 1);
            float gi = odd ? t2 : a0;
            float gf = odd ? t3 : a1;
            float gg = odd ? a2 : t0;
            float go = odd ? a3 : t1;
            int idx = half * 4 + n;
            float c = sigm(gf) * cs[mt][idx] + sigm(gi) * tanh_(gg);
            cs[mt][idx] = c;
            float h = sigm(go) * tanh_(c);
            unsigned short hh, hl;
            split2(h, hh, hl);
            hp[mt][idx] = (uint32_t)hh | ((uint32_t)hl << 16);
        }
    }
}

// ---------------- main persistent kernel ----------------
__global__ void __launch_bounds__(NT, 1)
decoder_kernel(const float* __restrict__ z,
               const float* __restrict__ w_lh, const float* __restrict__ b_lh,
               const float* __restrict__ w_lc, const float* __restrict__ b_lc,
               const float* __restrict__ b_proj,
               float* __restrict__ out) {
    extern __shared__ __align__(16) char smem[];
    uint16_t* Ah  = (uint16_t*)smem;                 // [32][AS] bf16 hi
    uint16_t* Al  = Ah + 32 * AS;                    // [32][AS] bf16 lo
    float*    pt  = (float*)(Al + 32 * AS);          // [8][32][33] proj partials
    float*    z_s = pt + 8 * 32 * 33;                // [32][32]

    const int tid  = threadIdx.x;
    const int wid  = tid >> 5;
    const int lane = tid & 31;
    const int tig  = lane & 3;
    const int odd  = lane & 1;
    const int r0   = blockIdx.x * ROWS;
    const int ubase  = wid * 16 + (tig >> 1);
    const int rbaseA = (lane >> 2) + (odd ? 8 : 0);

    // ---- stage z; init x-pad cols 0..31 (col 20 = 1.0 bias column) ----
    for (int i = tid; i < ROWS * LATD; i += NT) z_s[i] = z[(size_t)r0 * LATD + i];
    for (int i = tid; i < 32 * 32; i += NT) {
        int r = i >> 5, c = i & 31;
        Ah[r * AS + c] = (c == 20) ? (uint16_t)0x3F80 : (uint16_t)0;
        Al[r * AS + c] = 0;
    }
    __syncthreads();

    // ---- c-state init in C-fragment layout ----
    float c0st[2][8], c1st[2][8];
    #pragma unroll
    for (int nt = 0; nt < 8; ++nt) {
        int u = ubase + nt * 2;
        float s00 = b_lc[u], s01 = b_lc[HID + u];
        float s10 = s00,     s11 = s01;
        for (int k = 0; k < LATD; ++k) {
            float wa = __ldg(w_lc + (size_t)u * LATD + k);
            float wb = __ldg(w_lc + (size_t)(HID + u) * LATD + k);
            float z0 = z_s[rbaseA * LATD + k];
            float z1 = z_s[(16 + rbaseA) * LATD + k];
            s00 = fmaf(z0, wa, s00);  s01 = fmaf(z0, wb, s01);
            s10 = fmaf(z1, wa, s10);  s11 = fmaf(z1, wb, s11);
        }
        c0st[0][nt] = s00;  c1st[0][nt] = s01;
        c0st[1][nt] = s10;  c1st[1][nt] = s11;
    }

    // ---- h-state init into Ah/Al ----
    {
        int u2 = tid & 255, rb = (tid >> 8) * 16;
        float h0v[16], h1v[16];
        #pragma unroll
        for (int r = 0; r < 16; ++r) { h0v[r] = b_lh[u2]; h1v[r] = b_lh[HID + u2]; }
        for (int k = 0; k < LATD; ++k) {
            float wa = __ldg(w_lh + (size_t)u2 * LATD + k);
            float wb = __ldg(w_lh + (size_t)(HID + u2) * LATD + k);
            #pragma unroll
            for (int r = 0; r < 16; ++r) {
                float zv = z_s[(rb + r) * LATD + k];
                h0v[r] = fmaf(zv, wa, h0v[r]);
                h1v[r] = fmaf(zv, wb, h1v[r]);
            }
        }
        #pragma unroll
        for (int r = 0; r < 16; ++r) {
            unsigned short hh, hl;
            split2(h0v[r], hh, hl);
            Ah[(rb + r) * AS + H0C + u2] = hh;  Al[(rb + r) * AS + H0C + u2] = hl;
            split2(h1v[r], hh, hl);
            Ah[(rb + r) * AS + H1C + u2] = hh;  Al[(rb + r) * AS + H1C + u2] = hl;
        }
    }
    __syncthreads();

    const uint32_t aH = smem_u32(Ah) + (lane & 15) * ROWB + (lane >> 4) * 16;
    const uint32_t aL = smem_u32(Al) + (lane & 15) * ROWB + (lane >> 4) * 16;
    const uint4* wf0 = g_W0 + (size_t)wid * KS0 * 256 + lane;
    const uint4* wf1 = g_W1 + (size_t)wid * KS1 * 256 + lane;
    const uint4* wfP = g_PJ + (size_t)wid * 256 + lane;

    // =============================== time loop ===============================
    for (int t = 0; t < TST; ++t) {
        uint32_t hp[2][8];

        // ---- layer 0 : reads cols 0..287 ----
        #pragma unroll
        for (int half = 0; half < 2; ++half) {
            float acc[2][4][4];
            mma_half<KS0, 256>(aH, aL, wf0 + half * 128, acc);
            lstm_epi(acc, half, odd, c0st, hp);
        }
        __syncthreads();
        #pragma unroll
        for (int mt = 0; mt < 2; ++mt)
            #pragma unroll
            for (int nt = 0; nt < 8; ++nt) {
                int row = mt * 16 + rbaseA, u = ubase + nt * 2;
                Ah[row * AS + H0C + u] = (uint16_t)hp[mt][nt];
                Al[row * AS + H0C + u] = (uint16_t)(hp[mt][nt] >> 16);
            }
        __syncthreads();

        // ---- layer 1 : reads cols 16..543 ----
        #pragma unroll
        for (int half = 0; half < 2; ++half) {
            float acc[2][4][4];
            mma_half<KS1, 256>(aH + 32, aL + 32, wf1 + half * 128, acc);
            lstm_epi(acc, half, odd, c1st, hp);
        }
        __syncthreads();
        #pragma unroll
        for (int mt = 0; mt < 2; ++mt)
            #pragma unroll
            for (int nt = 0; nt < 8; ++nt) {
                int row = mt * 16 + rbaseA, u = ubase + nt * 2;
                Ah[row * AS + H1C + u] = (uint16_t)hp[mt][nt];
                Al[row * AS + H1C + u] = (uint16_t)(hp[mt][nt] >> 16);
            }
        __syncthreads();

        // ---- projection MMA: 8 warps K-split (K=32 each), partials -> SMEM ----
        if (wid < 8) {
            float acc[2][4][4];
            mma_half<2, 128>(aH + 2 * H1C + wid * 64, aL + 2 * H1C + wid * 64, wfP, acc);
            #pragma unroll
            for (int mt = 0; mt < 2; ++mt)
                #pragma unroll
                for (int n = 0; n < 4; ++n) {
                    int rr = mt * 16 + (lane >> 2);
                    float* p = pt + wid * 1056 + rr * 33 + n * 8 + tig * 2;
                    p[0]          = acc[mt][n][0];
                    p[1]          = acc[mt][n][1];
                    p[8 * 33]     = acc[mt][n][2];
                    p[8 * 33 + 1] = acc[mt][n][3];
                }
        }
        __syncthreads();

        // ---- reduce partials + bias, write gmem out, feed back as x ----
        for (int o = tid; o < ROWS * DIM; o += NT) {
            int r = o / DIM, d = o - r * DIM;
            float y = __ldg(b_proj + d);
            #pragma unroll
            for (int w8 = 0; w8 < 8; ++w8) y += pt[w8 * 1056 + r * 33 + d];
            out[(size_t)(r0 + r) * (TST * DIM) + (size_t)t * DIM + d] = y;
            unsigned short hh, hl;
            split2(y, hh, hl);
            Ah[r * AS + d] = hh;
            Al[r * AS + d] = hl;
        }
        __syncthreads();
    }
}

extern "C" void kernel_launch(void* const* d_in, const int* in_sizes, int n_in,
                              void* d_out, int out_size) {
    const int wbase = (n_in >= 17) ? 3 : 2;

    const float* z      = (const float*)d_in[0];
    const float* w_lh   = (const float*)d_in[wbase + 0];
    const float* b_lh   = (const float*)d_in[wbase + 1];
    const float* w_lc   = (const float*)d_in[wbase + 2];
    const float* b_lc   = (const float*)d_in[wbase + 3];
    const float* w_ih0  = (const float*)d_in[wbase + 4];
    const float* w_hh0  = (const float*)d_in[wbase + 5];
    const float* b_ih0  = (const float*)d_in[wbase + 6];
    const float* b_hh0  = (const float*)d_in[wbase + 7];
    const float* w_ih1  = (const float*)d_in[wbase + 8];
    const float* w_hh1  = (const float*)d_in[wbase + 9];
    const float* b_ih1  = (const float*)d_in[wbase + 10];
    const float* b_hh1  = (const float*)d_in[wbase + 11];
    const float* w_proj = (const float*)d_in[wbase + 12];
    const float* b_proj = (const float*)d_in[wbase + 13];

    static bool attr_set = false;
    if (!attr_set) {
        cudaFuncSetAttribute(decoder_kernel,
                             cudaFuncAttributeMaxDynamicSharedMemorySize, SMEM_BYTES);
        attr_set = true;
    }

    repack_kernel<<<512, 256>>>(w_ih0, w_hh0, b_ih0, b_hh0,
                                w_ih1, w_hh1, b_ih1, b_hh1, w_proj);
    decoder_kernel<<<NCTA, NT, SMEM_BYTES>>>(z, w_lh, b_lh, w_lc, b_lc,
                                             b_proj, (float*)d_out);
}

// round 8
// speedup vs baseline: 2.3528x; 1.4708x over previous
#include <cuda_runtime.h>
#include <cuda_bf16.h>
#include <cstdint>

#define BATCH   2048
#define LATD    32
#define HID     256
#define DIM     20
#define TST     512

#define ROWS    32                 // batch rows per CLUSTER
#define CLUSTER 2
#define NCTA    ((BATCH / ROWS) * CLUSTER)   // 128
#define NT      256                // 8 warps per CTA
#define NWCTA   8
#define NSLOT   16                 // global warp slots (column owners)

#define KS0     18                 // layer0: cols 0..287  (x|1|0|h0)
#define KS1     33                 // layer1: cols 16..543 (..|1|..|h0|h1)
#define AS      552                // u16 elements per activation row
#define ROWB    (AS * 2)           // bytes per row
#define MTOFF   (16 * ROWB)        // m-tile 1 byte offset
#define H0C     32
#define H1C     288

#define SMEM_BYTES (32*AS*2*2 + 8*32*33*4 + ROWS*LATD*4)   // 108544

// ---------------- fragment-major packed weights (repacked each launch) ----------------
__device__ uint4 g_W0[NSLOT * KS0 * 8 * 32];
__device__ uint4 g_W1[NSLOT * KS1 * 8 * 32];
__device__ uint4 g_PJ[8 * 2 * 4 * 32];

// ---------------- helpers ----------------
__device__ __forceinline__ float sigm(float x) {
    return __fdividef(1.f, 1.f + __expf(-x));
}
__device__ __forceinline__ float tanh_(float x) {
    float e = __expf(2.f * x);
    return 1.f - __fdividef(2.f, e + 1.f);
}
__device__ __forceinline__ void split2(float x, unsigned short& hi, unsigned short& lo) {
    __nv_bfloat16 h = __float2bfloat16_rn(x);
    hi = __bfloat16_as_ushort(h);
    lo = __bfloat16_as_ushort(__float2bfloat16_rn(x - __bfloat162float(h)));
}
__device__ __forceinline__ uint32_t smem_u32(const void* p) {
    uint32_t a;
    asm("{ .reg .u64 t; cvta.to.shared.u64 t, %1; cvt.u32.u64 %0, t; }" : "=r"(a) : "l"(p));
    return a;
}
__device__ __forceinline__ uint32_t mapa_sh(uint32_t addr, uint32_t rank) {
    uint32_t r;
    asm("mapa.shared::cluster.u32 %0, %1, %2;" : "=r"(r) : "r"(addr), "r"(rank));
    return r;
}
__device__ __forceinline__ void st_remote_u16(uint32_t addr, unsigned short v) {
    asm volatile("st.shared::cluster.u16 [%0], %1;" :: "r"(addr), "h"(v) : "memory");
}
__device__ __forceinline__ void cluster_sync_() {
    asm volatile("barrier.cluster.arrive.aligned;" ::: "memory");
    asm volatile("barrier.cluster.wait.aligned;" ::: "memory");
}
__device__ __forceinline__ void ldsm4(uint32_t& r0, uint32_t& r1, uint32_t& r2, uint32_t& r3,
                                      uint32_t a) {
    asm volatile("ldmatrix.sync.aligned.m8n8.x4.shared.b16 {%0,%1,%2,%3}, [%4];"
                 : "=r"(r0), "=r"(r1), "=r"(r2), "=r"(r3) : "r"(a));
}
__device__ __forceinline__ void mma16816(float* c, uint32_t a0, uint32_t a1, uint32_t a2,
                                         uint32_t a3, uint32_t b0, uint32_t b1) {
    asm volatile(
        "mma.sync.aligned.m16n8k16.row.col.f32.bf16.bf16.f32 "
        "{%0,%1,%2,%3}, {%4,%5,%6,%7}, {%8,%9}, {%0,%1,%2,%3};"
        : "+f"(c[0]), "+f"(c[1]), "+f"(c[2]), "+f"(c[3])
        : "r"(a0), "r"(a1), "r"(a2), "r"(a3), "r"(b0), "r"(b1));
}

// ---------------- repack: weight element accessors (kc = activation column) ----------------
__device__ __forceinline__ float W0val(int kc, int n,
                                       const float* w_ih0, const float* w_hh0,
                                       const float* b_ih0, const float* b_hh0) {
    int u = n >> 2, g = n & 3, row = g * HID + u;
    if (kc < DIM)  return w_ih0[row * DIM + kc];
    if (kc == 20)  return b_ih0[row] + b_hh0[row];
    if (kc < 32)   return 0.f;
    return w_hh0[row * HID + (kc - 32)];
}
__device__ __forceinline__ float W1val(int kc, int n,
                                       const float* w_ih1, const float* w_hh1,
                                       const float* b_ih1, const float* b_hh1) {
    int u = n >> 2, g = n & 3, row = g * HID + u;
    if (kc == 20)  return b_ih1[row] + b_hh1[row];
    if (kc >= 288) return w_hh1[row * HID + (kc - 288)];
    if (kc >= 32)  return w_ih1[row * HID + (kc - 32)];
    return 0.f;
}
__device__ __forceinline__ uint4 pack_frag(float e00, float e01, float e10, float e11) {
    unsigned short h00, l00, h01, l01, h10, l10, h11, l11;
    split2(e00, h00, l00); split2(e01, h01, l01);
    split2(e10, h10, l10); split2(e11, h11, l11);
    uint4 v;
    v.x = (uint32_t)h00 | ((uint32_t)h01 << 16);
    v.y = (uint32_t)h10 | ((uint32_t)h11 << 16);
    v.z = (uint32_t)l00 | ((uint32_t)l01 << 16);
    v.w = (uint32_t)l10 | ((uint32_t)l11 << 16);
    return v;
}

__global__ void repack_kernel(const float* __restrict__ w_ih0, const float* __restrict__ w_hh0,
                              const float* __restrict__ b_ih0, const float* __restrict__ b_hh0,
                              const float* __restrict__ w_ih1, const float* __restrict__ w_hh1,
                              const float* __restrict__ b_ih1, const float* __restrict__ b_hh1,
                              const float* __restrict__ w_proj) {
    const int stride = gridDim.x * blockDim.x;
    const int base   = blockIdx.x * blockDim.x + threadIdx.x;

    const int N0 = NSLOT * KS0 * 8 * 32;
    for (int idx = base; idx < N0; idx += stride) {
        int lane = idx & 31, t = idx >> 5;
        int nt = t & 7; t >>= 3;
        int ks = t % KS0, w = t / KS0;
        int n  = w * 64 + nt * 8 + (lane >> 2);
        int kc = ks * 16 + (lane & 3) * 2;
        g_W0[idx] = pack_frag(W0val(kc,     n, w_ih0, w_hh0, b_ih0, b_hh0),
                              W0val(kc + 1, n, w_ih0, w_hh0, b_ih0, b_hh0),
                              W0val(kc + 8, n, w_ih0, w_hh0, b_ih0, b_hh0),
                              W0val(kc + 9, n, w_ih0, w_hh0, b_ih0, b_hh0));
    }
    const int N1 = NSLOT * KS1 * 8 * 32;
    for (int idx = base; idx < N1; idx += stride) {
        int lane = idx & 31, t = idx >> 5;
        int nt = t & 7; t >>= 3;
        int ks = t % KS1, w = t / KS1;
        int n  = w * 64 + nt * 8 + (lane >> 2);
        int kc = 16 + ks * 16 + (lane & 3) * 2;
        g_W1[idx] = pack_frag(W1val(kc,     n, w_ih1, w_hh1, b_ih1, b_hh1),
                              W1val(kc + 1, n, w_ih1, w_hh1, b_ih1, b_hh1),
                              W1val(kc + 8, n, w_ih1, w_hh1, b_ih1, b_hh1),
                              W1val(kc + 9, n, w_ih1, w_hh1, b_ih1, b_hh1));
    }
    const int NP = 8 * 2 * 4 * 32;
    for (int idx = base; idx < NP; idx += stride) {
        int lane = idx & 31, t = idx >> 5;
        int nt = t & 3; t >>= 2;
        int ks = t & 1, w = t >> 1;
        int n  = nt * 8 + (lane >> 2);
        int kc = w * 32 + ks * 16 + (lane & 3) * 2;
        float e00 = (n < DIM) ? w_proj[n * HID + kc]     : 0.f;
        float e01 = (n < DIM) ? w_proj[n * HID + kc + 1] : 0.f;
        float e10 = (n < DIM) ? w_proj[n * HID + kc + 8] : 0.f;
        float e11 = (n < DIM) ? w_proj[n * HID + kc + 9] : 0.f;
        g_PJ[idx] = pack_frag(e00, e01, e10, e11);
    }
}

// ---------------- 3-pass bf16-split MMA over 4 n-tiles, 2 m-tiles, B prefetch ----------------
template <int KSTEPS, int KSTRIDE>
__device__ __forceinline__ void mma_half(uint32_t aHi, uint32_t aLo,
                                         const uint4* __restrict__ wf,
                                         float (&acc)[2][4][4]) {
    #pragma unroll
    for (int mt = 0; mt < 2; ++mt)
        #pragma unroll
        for (int n = 0; n < 4; ++n)
            #pragma unroll
            for (int i = 0; i < 4; ++i) acc[mt][n][i] = 0.f;

    uint4 B[4];
    #pragma unroll
    for (int n = 0; n < 4; ++n) B[n] = __ldg(wf + n * 32);

    #pragma unroll 2
    for (int ks = 0; ks < KSTEPS; ++ks) {
        uint4 Bn[4];
        if (ks + 1 < KSTEPS) {
            #pragma unroll
            for (int n = 0; n < 4; ++n)
                Bn[n] = __ldg(wf + (size_t)(ks + 1) * KSTRIDE + n * 32);
        }
        uint32_t h0, h1, h2, h3, h4, h5, h6, h7;
        uint32_t l0, l1, l2, l3, l4, l5, l6, l7;
        ldsm4(h0, h1, h2, h3, aHi + ks * 32);
        ldsm4(h4, h5, h6, h7, aHi + MTOFF + ks * 32);
        ldsm4(l0, l1, l2, l3, aLo + ks * 32);
        ldsm4(l4, l5, l6, l7, aLo + MTOFF + ks * 32);
        #pragma unroll
        for (int n = 0; n < 4; ++n) {
            mma16816(acc[0][n], h0, h1, h2, h3, B[n].x, B[n].y);   // hiA*hiB
            mma16816(acc[0][n], l0, l1, l2, l3, B[n].x, B[n].y);   // loA*hiB
            mma16816(acc[0][n], h0, h1, h2, h3, B[n].z, B[n].w);   // hiA*loB
            mma16816(acc[1][n], h4, h5, h6, h7, B[n].x, B[n].y);
            mma16816(acc[1][n], l4, l5, l6, l7, B[n].x, B[n].y);
            mma16816(acc[1][n], h4, h5, h6, h7, B[n].z, B[n].w);
        }
        #pragma unroll
        for (int n = 0; n < 4; ++n) B[n] = Bn[n];
    }
}

// ---------------- LSTM epilogue: gate regroup via lane-pair shuffle ----------------
__device__ __forceinline__ void lstm_epi(float (&acc)[2][4][4], int half, int odd,
                                         float (&cs)[2][8], uint32_t (&hp)[2][8]) {
    #pragma unroll
    for (int mt = 0; mt < 2; ++mt) {
        #pragma unroll
        for (int n = 0; n < 4; ++n) {
            float a0 = acc[mt][n][0], a1 = acc[mt][n][1];
            float a2 = acc[mt][n][2], a3 = acc[mt][n][3];
            float t0 = __shfl_xor_sync(0xffffffffu, a0, 1);
            float t1 = __shfl_xor_sync(0xffffffffu, a1, 1);
            float t2 = __shfl_xor_sync(0xffffffffu, a2, 1);
            float t3 = __shfl_xor_sync(0xffffffffu, a3, 1);
            float gi = odd ? t2 : a0;
            float gf = odd ? t3 : a1;
            float gg = odd ? a2 : t0;
            float go = odd ? a3 : t1;
            int idx = half * 4 + n;
            float c = sigm(gf) * cs[mt][idx] + sigm(gi) * tanh_(gg);
            cs[mt][idx] = c;
            float h = sigm(go) * tanh_(c);
            unsigned short hh, hl;
            split2(h, hh, hl);
            hp[mt][idx] = (uint32_t)hh | ((uint32_t)hl << 16);
        }
    }
}

// ---------------- main persistent clustered kernel ----------------
__global__ void __launch_bounds__(NT, 1) __cluster_dims__(CLUSTER, 1, 1)
decoder_kernel(const float* __restrict__ z,
               const float* __restrict__ w_lh, const float* __restrict__ b_lh,
               const float* __restrict__ w_lc, const float* __restrict__ b_lc,
               const float* __restrict__ b_proj,
               float* __restrict__ out) {
    extern __shared__ __align__(16) char smem[];
    uint16_t* Ah  = (uint16_t*)smem;                 // [32][AS] bf16 hi
    uint16_t* Al  = Ah + 32 * AS;                    // [32][AS] bf16 lo
    float*    pt  = (float*)(Al + 32 * AS);          // [8][32][33] proj partials
    float*    z_s = pt + 8 * 32 * 33;                // [32][32]

    const int tid  = threadIdx.x;
    const int wid  = tid >> 5;
    const int lane = tid & 31;
    const int tig  = lane & 3;
    const int odd  = lane & 1;
    uint32_t cr;
    asm("mov.u32 %0, %%cluster_ctarank;" : "=r"(cr));
    const int slot = (int)cr * NWCTA + wid;          // global column-owner slot
    const int r0   = (blockIdx.x / CLUSTER) * ROWS;
    const int ubase  = slot * 16 + (tig >> 1);
    const int rbaseA = (lane >> 2) + (odd ? 8 : 0);

    // ---- stage z; init x-pad cols 0..31 (col 20 = 1.0 bias column) ----
    for (int i = tid; i < ROWS * LATD; i += NT) z_s[i] = z[(size_t)r0 * LATD + i];
    for (int i = tid; i < 32 * 32; i += NT) {
        int r = i >> 5, c = i & 31;
        Ah[r * AS + c] = (c == 20) ? (uint16_t)0x3F80 : (uint16_t)0;
        Al[r * AS + c] = 0;
    }
    __syncthreads();

    // ---- c-state init in C-fragment layout (only own units) ----
    float c0st[2][8], c1st[2][8];
    #pragma unroll
    for (int nt = 0; nt < 8; ++nt) {
        int u = ubase + nt * 2;
        float s00 = b_lc[u], s01 = b_lc[HID + u];
        float s10 = s00,     s11 = s01;
        for (int k = 0; k < LATD; ++k) {
            float wa = __ldg(w_lc + (size_t)u * LATD + k);
            float wb = __ldg(w_lc + (size_t)(HID + u) * LATD + k);
            float z0 = z_s[rbaseA * LATD + k];
            float z1 = z_s[(16 + rbaseA) * LATD + k];
            s00 = fmaf(z0, wa, s00);  s01 = fmaf(z0, wb, s01);
            s10 = fmaf(z1, wa, s10);  s11 = fmaf(z1, wb, s11);
        }
        c0st[0][nt] = s00;  c1st[0][nt] = s01;
        c0st[1][nt] = s10;  c1st[1][nt] = s11;
    }

    // ---- h-state init into Ah/Al: each CTA fills the FULL A (redundant, init-only) ----
    {
        int u2 = tid;                                // 0..255 = all units
        for (int rb = 0; rb < 32; rb += 16) {
            float h0v[16], h1v[16];
            #pragma unroll
            for (int r = 0; r < 16; ++r) { h0v[r] = b_lh[u2]; h1v[r] = b_lh[HID + u2]; }
            for (int k = 0; k < LATD; ++k) {
                float wa = __ldg(w_lh + (size_t)u2 * LATD + k);
                float wb = __ldg(w_lh + (size_t)(HID + u2) * LATD + k);
                #pragma unroll
                for (int r = 0; r < 16; ++r) {
                    float zv = z_s[(rb + r) * LATD + k];
                    h0v[r] = fmaf(zv, wa, h0v[r]);
                    h1v[r] = fmaf(zv, wb, h1v[r]);
                }
            }
            #pragma unroll
            for (int r = 0; r < 16; ++r) {
                unsigned short hh, hl;
                split2(h0v[r], hh, hl);
                Ah[(rb + r) * AS + H0C + u2] = hh;  Al[(rb + r) * AS + H0C + u2] = hl;
                split2(h1v[r], hh, hl);
                Ah[(rb + r) * AS + H1C + u2] = hh;  Al[(rb + r) * AS + H1C + u2] = hl;
            }
        }
    }
    __syncthreads();

    const uint32_t AhB = smem_u32(Ah);
    const uint32_t AlB = smem_u32(Al);
    const uint32_t pAh = mapa_sh(AhB, cr ^ 1u);
    const uint32_t pAl = mapa_sh(AlB, cr ^ 1u);
    const uint32_t aH = AhB + (lane & 15) * ROWB + (lane >> 4) * 16;
    const uint32_t aL = AlB + (lane & 15) * ROWB + (lane >> 4) * 16;
    const uint4* wf0 = g_W0 + (size_t)slot * KS0 * 256 + lane;
    const uint4* wf1 = g_W1 + (size_t)slot * KS1 * 256 + lane;
    const uint4* wfP = g_PJ + (size_t)wid * 256 + lane;

    cluster_sync_();

    // =============================== time loop ===============================
    for (int t = 0; t < TST; ++t) {
        uint32_t hp[2][8];

        // ---- layer 0 : reads cols 0..287 ----
        #pragma unroll
        for (int half = 0; half < 2; ++half) {
            float acc[2][4][4];
            mma_half<KS0, 256>(aH, aL, wf0 + half * 128, acc);
            lstm_epi(acc, half, odd, c0st, hp);
        }
        cluster_sync_();                              // both CTAs done reading h0_old
        #pragma unroll
        for (int mt = 0; mt < 2; ++mt)
            #pragma unroll
            for (int nt = 0; nt < 8; ++nt) {
                int row = mt * 16 + rbaseA, u = ubase + nt * 2;
                uint32_t off = (uint32_t)(row * AS + H0C + u) * 2;
                unsigned short hh = (unsigned short)hp[mt][nt];
                unsigned short hl = (unsigned short)(hp[mt][nt] >> 16);
                Ah[row * AS + H0C + u] = hh;
                Al[row * AS + H0C + u] = hl;
                st_remote_u16(pAh + off, hh);
                st_remote_u16(pAl + off, hl);
            }
        cluster_sync_();                              // new h0 visible cluster-wide

        // ---- layer 1 : reads cols 16..543 ----
        #pragma unroll
        for (int half = 0; half < 2; ++half) {
            float acc[2][4][4];
            mma_half<KS1, 256>(aH + 32, aL + 32, wf1 + half * 128, acc);
            lstm_epi(acc, half, odd, c1st, hp);
        }
        cluster_sync_();                              // both CTAs done reading h1_old
        #pragma unroll
        for (int mt = 0; mt < 2; ++mt)
            #pragma unroll
            for (int nt = 0; nt < 8; ++nt) {
                int row = mt * 16 + rbaseA, u = ubase + nt * 2;
                uint32_t off = (uint32_t)(row * AS + H1C + u) * 2;
                unsigned short hh = (unsigned short)hp[mt][nt];
                unsigned short hl = (unsigned short)(hp[mt][nt] >> 16);
                Ah[row * AS + H1C + u] = hh;
                Al[row * AS + H1C + u] = hl;
                st_remote_u16(pAh + off, hh);
                st_remote_u16(pAl + off, hl);
            }
        cluster_sync_();                              // new h1 visible cluster-wide

        // ---- projection MMA: 8 warps K-split (K=32 each), partials -> SMEM ----
        {
            float acc[2][4][4];
            mma_half<2, 128>(aH + 2 * H1C + wid * 64, aL + 2 * H1C + wid * 64, wfP, acc);
            #pragma unroll
            for (int mt = 0; mt < 2; ++mt)
                #pragma unroll
                for (int n = 0; n < 4; ++n) {
                    int rr = mt * 16 + (lane >> 2);
                    float* p = pt + wid * 1056 + rr * 33 + n * 8 + tig * 2;
                    p[0]          = acc[mt][n][0];
                    p[1]          = acc[mt][n][1];
                    p[8 * 33]     = acc[mt][n][2];
                    p[8 * 33 + 1] = acc[mt][n][3];
                }
        }
        __syncthreads();

        // ---- reduce partials + bias; rank writes its half of rows to gmem; feed back x ----
        for (int o = tid; o < ROWS * DIM; o += NT) {
            int r = o / DIM, d = o - r * DIM;
            float y = __ldg(b_proj + d);
            #pragma unroll
            for (int w8 = 0; w8 < 8; ++w8) y += pt[w8 * 1056 + r * 33 + d];
            if ((uint32_t)(r >> 4) == cr)
                out[(size_t)(r0 + r) * (TST * DIM) + (size_t)t * DIM + d] = y;
            unsigned short hh, hl;
            split2(y, hh, hl);
            Ah[r * AS + d] = hh;
            Al[r * AS + d] = hl;
        }
        __syncthreads();
    }
}

extern "C" void kernel_launch(void* const* d_in, const int* in_sizes, int n_in,
                              void* d_out, int out_size) {
    const int wbase = (n_in >= 17) ? 3 : 2;

    const float* z      = (const float*)d_in[0];
    const float* w_lh   = (const float*)d_in[wbase + 0];
    const float* b_lh   = (const float*)d_in[wbase + 1];
    const float* w_lc   = (const float*)d_in[wbase + 2];
    const float* b_lc   = (const float*)d_in[wbase + 3];
    const float* w_ih0  = (const float*)d_in[wbase + 4];
    const float* w_hh0  = (const float*)d_in[wbase + 5];
    const float* b_ih0  = (const float*)d_in[wbase + 6];
    const float* b_hh0  = (const float*)d_in[wbase + 7];
    const float* w_ih1  = (const float*)d_in[wbase + 8];
    const float* w_hh1  = (const float*)d_in[wbase + 9];
    const float* b_ih1  = (const float*)d_in[wbase + 10];
    const float* b_hh1  = (const float*)d_in[wbase + 11];
    const float* w_proj = (const float*)d_in[wbase + 12];
    const float* b_proj = (const float*)d_in[wbase + 13];

    static bool attr_set = false;
    if (!attr_set) {
        cudaFuncSetAttribute(decoder_kernel,
                             cudaFuncAttributeMaxDynamicSharedMemorySize, SMEM_BYTES);
        attr_set = true;
    }

    repack_kernel<<<512, 256>>>(w_ih0, w_hh0, b_ih0, b_hh0,
                                w_ih1, w_hh1, b_ih1, b_hh1, w_proj);
    decoder_kernel<<<NCTA, NT, SMEM_BYTES>>>(z, w_lh, b_lh, w_lc, b_lc,
                                             b_proj, (float*)d_out);
}